// round 15
// baseline (speedup 1.0000x reference)
#include <cuda_runtime.h>
#include <math.h>
#include <stdint.h>

// EdgeEmbedding: pure elementwise map over edges (R0 analysis: the pair
// segment-mean and SH parity cancel bit-exactly):
//   edge_length    = ||edge_vec||
//   edge_embedding = bessel(||edge_vec||) * cutoff(||edge_vec||)
//   edge_attr      = SH_l<=2(edge_vec / ||edge_vec||)
// Output layout: [len (E) | emb (E,8) | attr (E,9)].
//
// R10 = R9 (warp-private staging, no block sync, coalesced float4 input,
// streaming hints, per-warp TMA bulk store for attr) with 128-thread
// blocks: everything is warp-private, so smaller blocks shrink the
// completion quantum (a block slot is held until its slowest warp's TMA
// wait retires) and raise achieved occupancy (was 79.7% of 64 warps).

#define TPB 128   // threads per block (4 warps); block-size-agnostic kernel
#define WPB (TPB / 32)

__device__ __forceinline__ void edge_math(float x, float y, float z,
                                          float& len, float* emb8, float* attr9)
{
    const float S3   = 1.7320508075688772f;   // sqrt(3)
    const float S5   = 2.2360679774997896f;   // sqrt(5)
    const float S15  = 3.8729833462074170f;   // sqrt(15)
    const float PI_F = 3.14159265358979323846f;
    const float SQRT_2_OVER_RC = 0.6324555320336759f; // sqrt(2/5)
    const float INV_RC = 0.2f;

    float r2  = fmaf(x, x, fmaf(y, y, z * z));
    float inv = rsqrtf(fmaxf(r2, 1e-24f));    // 1/r  (single MUFU.RSQ)
    float r   = r2 * inv;                     // r = r2 / sqrt(r2)
    len = r;

    // spherical harmonics l<=2 on u = vec/r
    float ux = x * inv, uy = y * inv, uz = z * inv;
    attr9[0] = 1.0f;
    attr9[1] = S3 * ux;
    attr9[2] = S3 * uy;
    attr9[3] = S3 * uz;
    attr9[4] = S15 * ux * uy;
    attr9[5] = S15 * uy * uz;
    attr9[6] = 0.5f * S5 * fmaf(3.0f * uz, uz, -1.0f);
    attr9[7] = S15 * ux * uz;
    attr9[8] = 0.5f * S15 * (ux * ux - uy * uy);

    // polynomial cutoff (p=6): 1 - 28 q^6 + 48 q^7 - 21 q^8
    float q  = r * INV_RC;
    float q2 = q * q;
    float q3 = q2 * q;
    float q6 = q3 * q3;
    float env = fmaf(q6, fmaf(q, fmaf(-21.0f, q, 48.0f), -28.0f), 1.0f);
    env = (q < 1.0f) ? env : 0.0f;

    // bessel: sqrt(2/RC) * sin(k*pi*q)/r_safe * env, k=1..8
    // Chebyshev recurrence: sin((k+1)t) = 2cos(t)sin(kt) - sin((k-1)t)
    float st, ct;
    __sincosf(PI_F * q, &st, &ct);            // MUFU sin/cos, |x| <= ~pi
    float pre  = SQRT_2_OVER_RC * inv * env;
    float twoc = 2.0f * ct;
    float sk_m1 = 0.0f, sk = st;
#pragma unroll
    for (int k = 0; k < 8; k++) {
        emb8[k] = pre * sk;
        float nxt = fmaf(twoc, sk, -sk_m1);
        sk_m1 = sk;
        sk = nxt;
    }
}

__device__ __forceinline__ uint32_t smem_u32(const void* p) {
    uint32_t a;
    asm("{ .reg .u64 t; cvta.to.shared.u64 t, %1; cvt.u32.u64 %0, t; }"
        : "=r"(a) : "l"(p));
    return a;
}

__global__ __launch_bounds__(TPB)
void edge_embed_r10(const float* __restrict__ vec,
                    float* __restrict__ out,
                    int E, int vec_ok)
{
    // per-warp slices (16B-aligned for TMA bulk store)
    __shared__ __align__(16) float in_s[WPB][96];     // 384B input per warp
    __shared__ __align__(16) float attr_s[WPB][288];  // 1152B attr per warp

    const int tid  = threadIdx.x;
    const int lane = tid & 31;
    const int wid  = tid >> 5;
    const long long base = (long long)blockIdx.x * TPB;
    const int nedge = (int)(((base + TPB) <= (long long)E)
                                ? (long long)TPB : ((long long)E - base));

    const bool warp_full = ((wid * 32 + 32) <= nedge) && vec_ok;
    const long long e = base + tid;

    float x, y, z;
    if (warp_full) {
        // warp-cooperative input: 24 lanes load the warp's 96 floats as
        // float4 (fully coalesced), stage, then conflict-free stride-3 LDS.
        const float4* v4 =
            reinterpret_cast<const float4*>(vec + (base + wid * 32) * 3);
        if (lane < 24)
            reinterpret_cast<float4*>(in_s[wid])[lane] = __ldcs(&v4[lane]);
        __syncwarp();
        x = in_s[wid][3 * lane + 0];
        y = in_s[wid][3 * lane + 1];
        z = in_s[wid][3 * lane + 2];
    } else if (tid < nedge) {
        x = vec[3 * e + 0];
        y = vec[3 * e + 1];
        z = vec[3 * e + 2];
    }

    if (tid < nedge) {
        float len, emb[8], a9[9];
        edge_math(x, y, z, len, emb, a9);

        // len: naturally coalesced
        __stcs(&out[e], len);

        // emb: direct from registers (each float4 is one thread's data)
        float* oe = out + (long long)E + e * 8;
        if (vec_ok) {
            float4* pe = reinterpret_cast<float4*>(oe);
            __stcs(&pe[0], make_float4(emb[0], emb[1], emb[2], emb[3]));
            __stcs(&pe[1], make_float4(emb[4], emb[5], emb[6], emb[7]));
        } else {
#pragma unroll
            for (int k = 0; k < 8; k++) oe[k] = emb[k];
        }

        if (warp_full) {
            // stage attr (stride-9 STS, 9 perp 32 -> conflict-free)
#pragma unroll
            for (int k = 0; k < 9; k++) attr_s[wid][lane * 9 + k] = a9[k];
        } else {
            // tail / unaligned: direct scalar stores (rare)
            float* oa = out + 9LL * E + e * 9;
#pragma unroll
            for (int k = 0; k < 9; k++) oa[k] = a9[k];
        }
    }

    if (warp_full) {
        __syncwarp();
        if (lane == 0) {
            // make generic-proxy STS visible to the async proxy, then bulk-
            // copy the warp's 1152B attr slice smem -> gmem via TMA engine.
            asm volatile("fence.proxy.async.shared::cta;" ::: "memory");
            uint32_t s = smem_u32(attr_s[wid]);
            float* g = out + 9LL * E + (base + wid * 32) * 9;  // 16B-aligned
            asm volatile(
                "cp.async.bulk.global.shared::cta.bulk_group [%0], [%1], %2;"
                :: "l"(g), "r"(s), "r"(1152u) : "memory");
            asm volatile("cp.async.bulk.commit_group;" ::: "memory");
            // smem must outlive the copy: wait for the engine's reads
            asm volatile("cp.async.bulk.wait_group.read 0;" ::: "memory");
        }
    }
}

extern "C" void kernel_launch(void* const* d_in, const int* in_sizes, int n_in,
                              void* d_out, int out_size)
{
    const float* edge_vec = (const float*)d_in[0];
    int E = in_sizes[0] / 3;
    float* out = (float*)d_out;

    // vectorized paths require 16B alignment of out+E (offset 8e), the attr
    // warp bases (9E + 9*32k), and input warp bases -> E % 4 == 0.
    int vec_ok = ((E & 3) == 0) ? 1 : 0;

    int blocks = (E + TPB - 1) / TPB;
    edge_embed_r10<<<blocks, TPB>>>(edge_vec, out, E, vec_ok);
}

// round 16
// speedup vs baseline: 1.0060x; 1.0060x over previous
#include <cuda_runtime.h>
#include <math.h>
#include <stdint.h>

// EdgeEmbedding: pure elementwise map over edges (R0 analysis: the pair
// segment-mean and SH parity cancel bit-exactly):
//   edge_length    = ||edge_vec||
//   edge_embedding = bessel(||edge_vec||) * cutoff(||edge_vec||)
//   edge_attr      = SH_l<=2(edge_vec / ||edge_vec||)
// Output layout: [len (E) | emb (E,8) | attr (E,9)].
//
// R11 = R9 (256-thr blocks, warp-private staging, no block sync, coalesced
// float4 input, streaming hints, attr via per-warp TMA bulk store) + emb
// ALSO via TMA: 2x STS.128 per thread into a 1024B warp slice (8 smem
// wavefronts vs 16 L1 wavefronts for the 32B-stride STG.128 path), then
// lane 0 issues both bulk stores in one commit group. R10's 128-thr blocks
// regressed and are reverted.

#define EPB 256   // edges per block == threads per block (8 warps)

__device__ __forceinline__ void edge_math(float x, float y, float z,
                                          float& len, float* emb8, float* attr9)
{
    const float S3   = 1.7320508075688772f;   // sqrt(3)
    const float S5   = 2.2360679774997896f;   // sqrt(5)
    const float S15  = 3.8729833462074170f;   // sqrt(15)
    const float PI_F = 3.14159265358979323846f;
    const float SQRT_2_OVER_RC = 0.6324555320336759f; // sqrt(2/5)
    const float INV_RC = 0.2f;

    float r2  = fmaf(x, x, fmaf(y, y, z * z));
    float inv = rsqrtf(fmaxf(r2, 1e-24f));    // 1/r  (single MUFU.RSQ)
    float r   = r2 * inv;                     // r = r2 / sqrt(r2)
    len = r;

    // spherical harmonics l<=2 on u = vec/r
    float ux = x * inv, uy = y * inv, uz = z * inv;
    attr9[0] = 1.0f;
    attr9[1] = S3 * ux;
    attr9[2] = S3 * uy;
    attr9[3] = S3 * uz;
    attr9[4] = S15 * ux * uy;
    attr9[5] = S15 * uy * uz;
    attr9[6] = 0.5f * S5 * fmaf(3.0f * uz, uz, -1.0f);
    attr9[7] = S15 * ux * uz;
    attr9[8] = 0.5f * S15 * (ux * ux - uy * uy);

    // polynomial cutoff (p=6): 1 - 28 q^6 + 48 q^7 - 21 q^8
    float q  = r * INV_RC;
    float q2 = q * q;
    float q3 = q2 * q;
    float q6 = q3 * q3;
    float env = fmaf(q6, fmaf(q, fmaf(-21.0f, q, 48.0f), -28.0f), 1.0f);
    env = (q < 1.0f) ? env : 0.0f;

    // bessel: sqrt(2/RC) * sin(k*pi*q)/r_safe * env, k=1..8
    // Chebyshev recurrence: sin((k+1)t) = 2cos(t)sin(kt) - sin((k-1)t)
    float st, ct;
    __sincosf(PI_F * q, &st, &ct);            // MUFU sin/cos, |x| <= ~pi
    float pre  = SQRT_2_OVER_RC * inv * env;
    float twoc = 2.0f * ct;
    float sk_m1 = 0.0f, sk = st;
#pragma unroll
    for (int k = 0; k < 8; k++) {
        emb8[k] = pre * sk;
        float nxt = fmaf(twoc, sk, -sk_m1);
        sk_m1 = sk;
        sk = nxt;
    }
}

__device__ __forceinline__ uint32_t smem_u32(const void* p) {
    uint32_t a;
    asm("{ .reg .u64 t; cvta.to.shared.u64 t, %1; cvt.u32.u64 %0, t; }"
        : "=r"(a) : "l"(p));
    return a;
}

__global__ __launch_bounds__(EPB)
void edge_embed_r11(const float* __restrict__ vec,
                    float* __restrict__ out,
                    int E, int vec_ok)
{
    // per-warp slices (16B-aligned for TMA bulk store)
    __shared__ __align__(16) float in_s[8][96];     // 384B  input per warp
    __shared__ __align__(16) float emb_s[8][256];   // 1024B emb   per warp
    __shared__ __align__(16) float attr_s[8][288];  // 1152B attr  per warp

    const int tid  = threadIdx.x;
    const int lane = tid & 31;
    const int wid  = tid >> 5;
    const long long base = (long long)blockIdx.x * EPB;
    const int nedge = (int)(((base + EPB) <= (long long)E)
                                ? (long long)EPB : ((long long)E - base));

    const bool warp_full = ((wid * 32 + 32) <= nedge) && vec_ok;
    const long long e = base + tid;

    float x, y, z;
    if (warp_full) {
        // warp-cooperative input: 24 lanes load the warp's 96 floats as
        // float4 (fully coalesced), stage, then conflict-free stride-3 LDS.
        const float4* v4 =
            reinterpret_cast<const float4*>(vec + (base + wid * 32) * 3);
        if (lane < 24)
            reinterpret_cast<float4*>(in_s[wid])[lane] = __ldcs(&v4[lane]);
        __syncwarp();
        x = in_s[wid][3 * lane + 0];
        y = in_s[wid][3 * lane + 1];
        z = in_s[wid][3 * lane + 2];
    } else if (tid < nedge) {
        x = vec[3 * e + 0];
        y = vec[3 * e + 1];
        z = vec[3 * e + 2];
    }

    if (tid < nedge) {
        float len, emb[8], a9[9];
        edge_math(x, y, z, len, emb, a9);

        // len: naturally coalesced
        __stcs(&out[e], len);

        if (warp_full) {
            // emb: stage as 2x STS.128 into the warp's 1024B slice
            float4* es = reinterpret_cast<float4*>(emb_s[wid]) + lane * 2;
            es[0] = make_float4(emb[0], emb[1], emb[2], emb[3]);
            es[1] = make_float4(emb[4], emb[5], emb[6], emb[7]);
            // attr: stage (stride-9 STS, 9 perp 32 -> conflict-free)
#pragma unroll
            for (int k = 0; k < 9; k++) attr_s[wid][lane * 9 + k] = a9[k];
        } else {
            // tail / unaligned: direct scalar stores (rare)
            float* oe = out + (long long)E + e * 8;
#pragma unroll
            for (int k = 0; k < 8; k++) oe[k] = emb[k];
            float* oa = out + 9LL * E + e * 9;
#pragma unroll
            for (int k = 0; k < 9; k++) oa[k] = a9[k];
        }
    }

    if (warp_full) {
        __syncwarp();
        if (lane == 0) {
            // make generic-proxy STS visible to the async proxy, then bulk-
            // copy both warp slices smem -> gmem via the TMA engine.
            asm volatile("fence.proxy.async.shared::cta;" ::: "memory");
            uint32_t se = smem_u32(emb_s[wid]);
            uint32_t sa = smem_u32(attr_s[wid]);
            float* ge = out + (long long)E + (base + wid * 32) * 8;
            float* ga = out + 9LL * E + (base + wid * 32) * 9;
            asm volatile(
                "cp.async.bulk.global.shared::cta.bulk_group [%0], [%1], %2;"
                :: "l"(ge), "r"(se), "r"(1024u) : "memory");
            asm volatile(
                "cp.async.bulk.global.shared::cta.bulk_group [%0], [%1], %2;"
                :: "l"(ga), "r"(sa), "r"(1152u) : "memory");
            asm volatile("cp.async.bulk.commit_group;" ::: "memory");
            // smem must outlive the copies: wait for the engine's reads
            asm volatile("cp.async.bulk.wait_group.read 0;" ::: "memory");
        }
    }
}

extern "C" void kernel_launch(void* const* d_in, const int* in_sizes, int n_in,
                              void* d_out, int out_size)
{
    const float* edge_vec = (const float*)d_in[0];
    int E = in_sizes[0] / 3;
    float* out = (float*)d_out;

    // vectorized paths require 16B alignment of out+E (offset 8e), the attr
    // warp bases (9E + 9*32k), and input warp bases -> E % 4 == 0.
    int vec_ok = ((E & 3) == 0) ? 1 : 0;

    int blocks = (E + EPB - 1) / EPB;
    edge_embed_r11<<<blocks, EPB>>>(edge_vec, out, E, vec_ok);
}